// round 16
// baseline (speedup 1.0000x reference)
#include <cuda_runtime.h>

#define NN 50000
#define NE 800000
#define HH 64

// Scratch (no runtime allocation allowed)
__device__ __align__(16) float g_u[NN * HH];      // h @ W1d^T
__device__ __align__(16) float g_p[NN * HH];      // nf @ W1a^T
__device__ __align__(16) float g_q[NN * HH];      // nf @ W1b^T
__device__ __align__(16) float g_efs[NN * 16];    // per-dst ef sums (RED in scatter)

// CSR build scratch
__device__ int  g_cnt[NN];      // zero at load; re-zeroed by scan1 each run
__device__ int  g_off[NN + 1];
__device__ int  g_cur[NN];
__device__ int  g_bsum[64];
__device__ int  g_esrc[NE];     // src, sorted by dst

// Pre-transposed weights for finalize (filled by launch-1 hist block 0)
__device__ __align__(16) float g_W1cT[16 * 64];   // [k][j] = W1[j][64+k]
__device__ __align__(16) float g_W2T[64 * 64];    // [j][i] = W2[i][j]

__device__ __forceinline__ void fma4(float4& a, float x, const float4& wv) {
    a.x = fmaf(x, wv.x, a.x);
    a.y = fmaf(x, wv.y, a.y);
    a.z = fmaf(x, wv.z, a.z);
    a.w = fmaf(x, wv.w, a.w);
}

__device__ __forceinline__ void add4(float4& a, const float4& b) {
    a.x += b.x; a.y += b.y; a.z += b.z; a.w += b.w;
}

// ---------------------------------------------------------------------------
// Launch 1 (striped): hist | pq GEMM | u GEMM.
//   hist id in [0, gh):    zero g_efs, atomic histogram of dst; id 0 also
//                          transposes W1c/W2 for the finalize kernel.
//   gemm id in [0, gpq):   [p|q] = nf @ [W1a^T|W1b^T], 64-node tile
//   gemm id in [gpq, ..):  u = h @ W1d^T, 64-node tile
// GEMM branches stage weights directly from W1 (coalesced LDG; the strided
// STS transpose costs a few hundred wavefronts per block — negligible).
// Hist blocks are latency-light and hide fully under the FMA-bound GEMMs.
// Relies on g_cnt == 0 on entry (zero-init at load; scan1 re-zeroes each run).
// ---------------------------------------------------------------------------
__global__ __launch_bounds__(256) void fused1_kernel(
    const int* __restrict__ dst, const float* __restrict__ W1,
    const float* __restrict__ W2,
    const float* __restrict__ nf, const float* __restrict__ h,
    int N, int E, int gh, int gpq, int G)
{
    __shared__ __align__(16) char smem_raw[24576];
    int b = blockIdx.x;

    long long t0 = (long long)b * gh / G;
    long long t1 = (long long)(b + 1) * gh / G;
    bool is_hist = (t1 > t0);
    int id = is_hist ? (int)t0 : (int)(b - t0);

    if (is_hist) {
        int i = id * 256 + threadIdx.x;
        // zero g_efs (one float4 per thread; gh*256 >= NN*4)
        if (i < NN * 4)
            reinterpret_cast<float4*>(g_efs)[i] = make_float4(0.f, 0.f, 0.f, 0.f);
        if (i < E)
            atomicAdd(&g_cnt[__ldg(&dst[i])], 1);

        if (id == 0) {
            // transpose W1c and W2 for the finalize kernel
            for (int idx = threadIdx.x; idx < 16 * 64; idx += 256) {
                int k = idx >> 6, j = idx & 63;
                g_W1cT[k * 64 + j] = W1[j * 144 + 64 + k];
            }
            for (int idx = threadIdx.x; idx < 64 * 64; idx += 256) {
                int i2 = idx >> 6, j = idx & 63;
                g_W2T[j * 64 + i2] = W2[idx];
            }
        }
        return;
    }

    if (id < gpq) {
        // ---- pq GEMM: 64 nodes x 128 outputs, K=32, acc[8] ----
        float* sW = reinterpret_cast<float*>(smem_raw);            // 32*128 = 16KB
        float* sX = reinterpret_cast<float*>(smem_raw + 16384);    // 64*32  = 8KB

        // stage W1a|W1b transposed: sW[k][j'] with j'<64 -> a, j'>=64 -> b
        for (int idx = threadIdx.x; idx < 4096; idx += 256) {
            int j = idx >> 6, k2 = idx & 63;       // coalesced LDG over k2
            float w = W1[j * 144 + k2];
            if (k2 < 32) sW[k2 * 128 + j] = w;
            else         sW[(k2 - 32) * 128 + 64 + j] = w;
        }

        int n0 = id * 64;
        const float4* nf4 = reinterpret_cast<const float4*>(nf);
        float4* sX4 = reinterpret_cast<float4*>(sX);
        for (int idx = threadIdx.x; idx < 512; idx += 256) {
            int n = n0 + (idx >> 3);
            sX4[idx] = (n < N) ? __ldg(&nf4[n * 8 + (idx & 7)])
                               : make_float4(0.f, 0.f, 0.f, 0.f);
        }
        __syncthreads();

        int jg = threadIdx.x & 31;
        int ng = threadIdx.x >> 5;
        const float* xb = sX + ng * 8 * 32;
        const float4* sW4 = reinterpret_cast<const float4*>(sW);

        float4 acc[8];
        #pragma unroll
        for (int i = 0; i < 8; i++) acc[i] = make_float4(0.f, 0.f, 0.f, 0.f);

        #pragma unroll 8
        for (int k = 0; k < 32; k++) {
            float4 wv = sW4[k * 32 + jg];
            #pragma unroll
            for (int i = 0; i < 8; i++) fma4(acc[i], xb[i * 32 + k], wv);
        }

        float4* dst4 = (jg < 16) ? reinterpret_cast<float4*>(g_p)
                                 : reinterpret_cast<float4*>(g_q);
        int jj = jg & 15;
        #pragma unroll
        for (int i = 0; i < 8; i++) {
            int n = n0 + ng * 8 + i;
            if (n < N) dst4[n * 16 + jj] = acc[i];
        }
        return;
    }

    // ---- u GEMM: 64 nodes x 64 outputs, K=64, acc[4] ----
    {
        int bid = id - gpq;
        float* sW = reinterpret_cast<float*>(smem_raw);            // 64*64 = 16KB
        float* sX = reinterpret_cast<float*>(smem_raw + 16384);    // 64*16*... 64*64? no: 64 nodes x 16 float4 = 4KB? (64*64 floats? no: 64 nodes, K=64 -> 16KB? fits: 16384+16384 > 24576) -- use 8KB offset carefully
        // NOTE: sX needs 64 nodes * 64 K * 4B = 16KB; total 32KB > 24KB buffer.
        // Split: reuse layout 16KB sW + 8KB half-tile, process 32 nodes per pass.
        (void)sX;

        // stage W1d transposed: sW[k][j] = W1[j][80+k]
        for (int idx = threadIdx.x; idx < 4096; idx += 256) {
            int j = idx >> 6, k = idx & 63;        // coalesced LDG over k
            sW[k * 64 + j] = W1[j * 144 + 80 + k];
        }

        const float4* h4 = reinterpret_cast<const float4*>(h);
        float4* du4 = reinterpret_cast<float4*>(g_u);
        const float4* sW4 = reinterpret_cast<const float4*>(sW);
        float* sXh = reinterpret_cast<float*>(smem_raw + 16384);   // 32 nodes x 64 = 8KB

        #pragma unroll
        for (int half = 0; half < 2; half++) {
            int n0 = bid * 64 + half * 32;
            float4* sXh4 = reinterpret_cast<float4*>(sXh);
            __syncthreads();
            for (int idx = threadIdx.x; idx < 512; idx += 256) {
                int n = n0 + (idx >> 4);
                sXh4[idx] = (n < N) ? __ldg(&h4[n * 16 + (idx & 15)])
                                    : make_float4(0.f, 0.f, 0.f, 0.f);
            }
            __syncthreads();

            int jg = threadIdx.x & 15;    // 16 x 4 outputs = 64 outputs
            int ng = threadIdx.x >> 4;    // 16 groups x 2 nodes = 32 nodes
            const float* xb = sXh + ng * 2 * 64;

            float4 acc[2];
            acc[0] = make_float4(0.f, 0.f, 0.f, 0.f);
            acc[1] = make_float4(0.f, 0.f, 0.f, 0.f);

            #pragma unroll 8
            for (int k = 0; k < 64; k++) {
                float4 wv = sW4[k * 16 + jg];
                fma4(acc[0], xb[k], wv);
                fma4(acc[1], xb[64 + k], wv);
            }

            #pragma unroll
            for (int i = 0; i < 2; i++) {
                int n = n0 + ng * 2 + i;
                if (n < N) du4[n * 16 + jg] = acc[i];
            }
        }
    }
}

// ---------------------------------------------------------------------------
// Launch 2: per-1024-chunk exclusive scan + chunk totals; re-zero g_cnt.
// ---------------------------------------------------------------------------
__global__ __launch_bounds__(1024) void scan1_kernel()
{
    __shared__ int s[1024];
    int tid = threadIdx.x;
    int idx = blockIdx.x * 1024 + tid;
    int v = 0;
    if (idx < NN) {
        v = g_cnt[idx];
        g_cnt[idx] = 0;          // reset for next run (graph replay invariant)
    }
    s[tid] = v;
    __syncthreads();
    #pragma unroll
    for (int d = 1; d < 1024; d <<= 1) {
        int t = (tid >= d) ? s[tid - d] : 0;
        __syncthreads();
        s[tid] += t;
        __syncthreads();
    }
    if (idx < NN) g_off[idx] = s[tid] - v;   // exclusive (within chunk)
    if (tid == 1023) g_bsum[blockIdx.x] = s[1023];
}

// ---------------------------------------------------------------------------
// Launch 3: add chunk-prefix; fill g_cur. (Must finish before any scatter.)
// ---------------------------------------------------------------------------
__global__ __launch_bounds__(1024) void scan2_kernel(int E)
{
    int b = blockIdx.x, tid = threadIdx.x;
    int idx = b * 1024 + tid;
    int add = 0;
    for (int j = 0; j < b; j++) add += g_bsum[j];   // uniform, tiny
    if (idx < NN) {
        int v = g_off[idx] + add;
        g_off[idx] = v;
        g_cur[idx] = v;
    }
    if (b == 0 && tid == 0) g_off[NN] = E;
}

// ---------------------------------------------------------------------------
// Launch 4: scatter src into dst-sorted slots + RED ef sums per dst.
// Standalone: reg-light -> high occupancy hides atomic/RED latency.
// ---------------------------------------------------------------------------
__global__ __launch_bounds__(256) void scatter_kernel(
    const int* __restrict__ src, const int* __restrict__ dst,
    const float* __restrict__ ef, int E)
{
    int i = blockIdx.x * blockDim.x + threadIdx.x;
    if (i >= E) return;
    int d = __ldg(&dst[i]);
    int pos = atomicAdd(&g_cur[d], 1);
    g_esrc[pos] = __ldg(&src[i]);

    const float4* ef4 = reinterpret_cast<const float4*>(ef);
    float4* efs4 = reinterpret_cast<float4*>(g_efs);
    #pragma unroll
    for (int c = 0; c < 4; c++)
        atomicAdd(&efs4[d * 4 + c], __ldg(&ef4[i * 4 + c]));
}

// ---------------------------------------------------------------------------
// Launch 5: fused gather + finalize, 2-way edge-parallel lanes, pure-u loop.
// Warp = 2 edge slots x 16 float4 lanes; unroll 4 pairs (8 edges in flight).
// y = u_sum + p + deg*q + W1c@efs; relu; staged 4-node W2 GEMM.
// ---------------------------------------------------------------------------
__global__ __launch_bounds__(256) void gather_finalize_kernel(
    const float* __restrict__ h, float* __restrict__ out, int N)
{
    __shared__ float sW1cT[16 * 64];
    __shared__ float sW2T[64 * 64];
    __shared__ __align__(16) float sY[8][4 * 64];
    __shared__ float sEf[8][4 * 16];

    for (int idx = threadIdx.x; idx < 16 * 64; idx += 256) sW1cT[idx] = g_W1cT[idx];
    for (int idx = threadIdx.x; idx < 64 * 64; idx += 256) sW2T[idx]  = g_W2T[idx];
    __syncthreads();

    int lane = threadIdx.x & 31;
    int warp = threadIdx.x >> 5;
    int slot = lane >> 4;          // 0 or 1
    int f4   = lane & 15;          // float4 index within 64-float row
    int gw = (blockIdx.x * blockDim.x + threadIdx.x) >> 5;
    int nb = gw * 4;
    if (nb >= N) return;
    int cnt = min(4, N - nb);

    const float4* u4 = reinterpret_cast<const float4*>(g_u);
    float dgv[4];

    for (int m = 0; m < cnt; m++) {
        int n = nb + m;
        int off0 = __ldg(&g_off[n]);
        int off1 = __ldg(&g_off[n + 1]);
        dgv[m] = (float)(off1 - off0);

        float4 acc = make_float4(0.f, 0.f, 0.f, 0.f);

        int i = off0;
        for (; i + 8 <= off1; i += 8) {
            int sA = __ldg(&g_esrc[i     + slot]);
            int sB = __ldg(&g_esrc[i + 2 + slot]);
            int sC = __ldg(&g_esrc[i + 4 + slot]);
            int sD = __ldg(&g_esrc[i + 6 + slot]);
            float4 vA = __ldg(&u4[sA * 16 + f4]);
            float4 vB = __ldg(&u4[sB * 16 + f4]);
            float4 vC = __ldg(&u4[sC * 16 + f4]);
            float4 vD = __ldg(&u4[sD * 16 + f4]);
            add4(acc, vA); add4(acc, vB); add4(acc, vC); add4(acc, vD);
        }
        for (; i + 2 <= off1; i += 2) {
            int s = __ldg(&g_esrc[i + slot]);
            float4 v = __ldg(&u4[s * 16 + f4]);
            add4(acc, v);
        }
        if (i < off1 && slot == 0) {   // odd remainder: slot-0 lanes only
            int s = __ldg(&g_esrc[i]);
            float4 v = __ldg(&u4[s * 16 + f4]);
            add4(acc, v);
        }

        // merge slot 0 + slot 1
        acc.x += __shfl_xor_sync(0xffffffffu, acc.x, 16);
        acc.y += __shfl_xor_sync(0xffffffffu, acc.y, 16);
        acc.z += __shfl_xor_sync(0xffffffffu, acc.z, 16);
        acc.w += __shfl_xor_sync(0xffffffffu, acc.w, 16);

        if (lane < 16) {
            reinterpret_cast<float4*>(&sY[warp][m * 64])[f4] = acc;
            sEf[warp][m * 16 + lane] = __ldg(&g_efs[n * 16 + lane]);
        }
        __syncwarp();

        float dg = dgv[m];
        float y0 = sY[warp][m * 64 + lane]
                 + g_p[n * 64 + lane]      + dg * g_q[n * 64 + lane];
        float y1 = sY[warp][m * 64 + lane + 32]
                 + g_p[n * 64 + lane + 32] + dg * g_q[n * 64 + lane + 32];

        #pragma unroll
        for (int k = 0; k < 16; k++) {
            float mk = sEf[warp][m * 16 + k];
            y0 = fmaf(mk, sW1cT[k * 64 + lane],      y0);
            y1 = fmaf(mk, sW1cT[k * 64 + lane + 32], y1);
        }
        sY[warp][m * 64 + lane]      = fmaxf(y0, 0.f);
        sY[warp][m * 64 + lane + 32] = fmaxf(y1, 0.f);
    }
    __syncwarp();

    float o0[4] = {0.f, 0.f, 0.f, 0.f};
    float o1[4] = {0.f, 0.f, 0.f, 0.f};
    #pragma unroll
    for (int j = 0; j < 64; j++) {
        float w0 = sW2T[j * 64 + lane];
        float w1 = sW2T[j * 64 + lane + 32];
        #pragma unroll
        for (int m = 0; m < 4; m++) {
            float yj = sY[warp][m * 64 + j];
            o0[m] = fmaf(yj, w0, o0[m]);
            o1[m] = fmaf(yj, w1, o1[m]);
        }
    }

    for (int m = 0; m < cnt; m++) {
        int n = nb + m;
        if (dgv[m] > 0.f) {
            out[n * 64 + lane]      = o0[m];
            out[n * 64 + lane + 32] = o1[m];
        } else {
            out[n * 64 + lane]      = h[n * 64 + lane];
            out[n * 64 + lane + 32] = h[n * 64 + lane + 32];
        }
    }
}

// ---------------------------------------------------------------------------
extern "C" void kernel_launch(void* const* d_in, const int* in_sizes, int n_in,
                              void* d_out, int out_size)
{
    const float* h  = (const float*)d_in[0];
    const float* nf = (const float*)d_in[1];
    const float* ef = (const float*)d_in[2];
    const int*  src = (const int*)d_in[3];
    const int*  dst = (const int*)d_in[4];
    const float* W1 = (const float*)d_in[5];
    const float* W2 = (const float*)d_in[6];
    float* out = (float*)d_out;

    int N = in_sizes[1] / 32;   // nf is [N, 32]
    int E = in_sizes[3];        // src is [E]

    int gh   = (E + 255) / 256;        // hist blocks (covers NN*4 zeroing too)
    int gsc  = (NN + 1023) / 1024;     // 49
    int gpq  = (N + 63) / 64;
    int gu   = (N + 63) / 64;
    int G1   = gh + gpq + gu;
    int ge   = (E + 255) / 256;
    int gf   = (N + 31) / 32;

    fused1_kernel<<<G1, 256>>>(dst, W1, W2, nf, h, N, E, gh, gpq, G1);
    scan1_kernel<<<gsc, 1024>>>();
    scan2_kernel<<<gsc, 1024>>>(E);
    scatter_kernel<<<ge, 256>>>(src, dst, ef, E);
    gather_finalize_kernel<<<gf, 256>>>(h, out, N);
}

// round 17
// speedup vs baseline: 1.0578x; 1.0578x over previous
#include <cuda_runtime.h>

#define NN 50000
#define NE 800000
#define HH 64

// Scratch (no runtime allocation allowed)
__device__ __align__(16) float g_u[NN * HH];      // h @ W1d^T
__device__ __align__(16) float g_p[NN * HH];      // nf @ W1a^T
__device__ __align__(16) float g_q[NN * HH];      // nf @ W1b^T
__device__ __align__(16) float g_efs[NN * 16];    // per-dst ef sums (RED in scatter)

// CSR build scratch
__device__ int  g_cnt[NN];      // zero at load; re-zeroed by scan1 each run
__device__ int  g_off[NN + 1];
__device__ int  g_cur[NN];
__device__ int  g_bsum[64];
__device__ int  g_esrc[NE];     // src, sorted by dst

// Pre-transposed weights (filled by hist_kernel block 0)
__device__ __align__(16) float g_WpqT[32 * 128];  // [k][j]: j<64 -> W1a, j>=64 -> W1b
__device__ __align__(16) float g_WuT[64 * 64];    // [k][j] = W1[j][80+k]
__device__ __align__(16) float g_W1cT[16 * 64];   // [k][j] = W1[j][64+k]
__device__ __align__(16) float g_W2T[64 * 64];    // [j][i] = W2[i][j]

__device__ __forceinline__ void fma4(float4& a, float x, const float4& wv) {
    a.x = fmaf(x, wv.x, a.x);
    a.y = fmaf(x, wv.y, a.y);
    a.z = fmaf(x, wv.z, a.z);
    a.w = fmaf(x, wv.w, a.w);
}

__device__ __forceinline__ void add4(float4& a, const float4& b) {
    a.x += b.x; a.y += b.y; a.z += b.z; a.w += b.w;
}

// Branchy node-select accumulate: edges are dst-sorted, so nd is near-uniform
// across the warp (divergence only at node boundaries).
__device__ __forceinline__ void accum_sel(
    int pos, const float4& v, int o1, int o2, int o3,
    float4& a0, float4& a1, float4& a2, float4& a3)
{
    int nd = (pos >= o1) + (pos >= o2) + (pos >= o3);
    if (nd == 0)      add4(a0, v);
    else if (nd == 1) add4(a1, v);
    else if (nd == 2) add4(a2, v);
    else              add4(a3, v);
}

// ---------------------------------------------------------------------------
// Launch 1: histogram of dst + zero g_efs; block 0 also transposes weights.
// Relies on g_cnt == 0 on entry (zero-init at load; scan1 re-zeroes each run).
// ---------------------------------------------------------------------------
__global__ __launch_bounds__(256) void hist_kernel(
    const int* __restrict__ dst, const float* __restrict__ W1,
    const float* __restrict__ W2, int E)
{
    int tid = blockIdx.x * blockDim.x + threadIdx.x;
    int stride = gridDim.x * blockDim.x;

    float4* efs4 = reinterpret_cast<float4*>(g_efs);
    float4 z = make_float4(0.f, 0.f, 0.f, 0.f);
    for (int i = tid; i < NN * 4; i += stride) efs4[i] = z;

    if (tid < E) atomicAdd(&g_cnt[__ldg(&dst[tid])], 1);

    if (blockIdx.x == 0) {
        for (int idx = threadIdx.x; idx < 64 * 144; idx += 256) {
            int j = idx / 144, k = idx % 144;
            float w = W1[idx];
            if (k < 32)       g_WpqT[k * 128 + j] = w;
            else if (k < 64)  g_WpqT[(k - 32) * 128 + 64 + j] = w;
            else if (k < 80)  g_W1cT[(k - 64) * 64 + j] = w;
            else              g_WuT[(k - 80) * 64 + j] = w;
        }
        for (int idx = threadIdx.x; idx < 64 * 64; idx += 256) {
            int i = idx >> 6, j = idx & 63;
            g_W2T[j * 64 + i] = W2[idx];
        }
    }
}

// ---------------------------------------------------------------------------
// Launch 2: per-1024-chunk exclusive scan + chunk totals; re-zero g_cnt.
// ---------------------------------------------------------------------------
__global__ __launch_bounds__(1024) void scan1_kernel()
{
    __shared__ int s[1024];
    int tid = threadIdx.x;
    int idx = blockIdx.x * 1024 + tid;
    int v = 0;
    if (idx < NN) {
        v = g_cnt[idx];
        g_cnt[idx] = 0;          // reset for next run (graph replay invariant)
    }
    s[tid] = v;
    __syncthreads();
    #pragma unroll
    for (int d = 1; d < 1024; d <<= 1) {
        int t = (tid >= d) ? s[tid - d] : 0;
        __syncthreads();
        s[tid] += t;
        __syncthreads();
    }
    if (idx < NN) g_off[idx] = s[tid] - v;   // exclusive (within chunk)
    if (tid == 1023) g_bsum[blockIdx.x] = s[1023];
}

// ---------------------------------------------------------------------------
// Launch 3: add chunk-prefix; fill g_cur. (Must finish before any scatter.)
// ---------------------------------------------------------------------------
__global__ __launch_bounds__(1024) void scan2_kernel(int E)
{
    int b = blockIdx.x, tid = threadIdx.x;
    int idx = b * 1024 + tid;
    int add = 0;
    for (int j = 0; j < b; j++) add += g_bsum[j];   // uniform, tiny
    if (idx < NN) {
        int v = g_off[idx] + add;
        g_off[idx] = v;
        g_cur[idx] = v;
    }
    if (b == 0 && tid == 0) g_off[NN] = E;
}

// ---------------------------------------------------------------------------
// Launch 4 (striped block-partitioned fusion): scatter | pq GEMM | u GEMM.
// Bresenham-interleaved roles: every dispatch wave carries a proportional mix
// of scatter (latency-bound) and GEMM (FMA-bound) blocks.
// ---------------------------------------------------------------------------
__global__ __launch_bounds__(256) void fused4_kernel(
    const int* __restrict__ src, const int* __restrict__ dst,
    const float* __restrict__ ef,
    const float* __restrict__ nf, const float* __restrict__ h,
    int N, int E, int gs, int gpq, int G)
{
    __shared__ __align__(16) char smem_raw[32768];
    int b = blockIdx.x;

    long long t0 = (long long)b * gs / G;
    long long t1 = (long long)(b + 1) * gs / G;
    bool is_scatter = (t1 > t0);
    int id = is_scatter ? (int)t0 : (int)(b - t0);

    if (is_scatter) {
        // ---- scatter ----
        int i = id * 256 + threadIdx.x;
        if (i >= E) return;
        int d = __ldg(&dst[i]);
        int pos = atomicAdd(&g_cur[d], 1);
        g_esrc[pos] = __ldg(&src[i]);

        const float4* ef4 = reinterpret_cast<const float4*>(ef);
        float4* efs4 = reinterpret_cast<float4*>(g_efs);
        #pragma unroll
        for (int c = 0; c < 4; c++)
            atomicAdd(&efs4[d * 4 + c], __ldg(&ef4[i * 4 + c]));
        return;
    }

    if (id < gpq) {
        // ---- pq GEMM: 64 nodes x 128 outputs, K=32, acc[8] ----
        int bid = id;
        float* sW = reinterpret_cast<float*>(smem_raw);            // 32*128 = 16KB
        float* sX = reinterpret_cast<float*>(smem_raw + 16384);    // 64*32  = 8KB

        for (int idx = threadIdx.x; idx < 32 * 128; idx += 256)
            sW[idx] = g_WpqT[idx];

        int n0 = bid * 64;
        const float4* nf4 = reinterpret_cast<const float4*>(nf);
        float4* sX4 = reinterpret_cast<float4*>(sX);
        for (int idx = threadIdx.x; idx < 512; idx += 256) {
            int n = n0 + (idx >> 3);
            sX4[idx] = (n < N) ? __ldg(&nf4[n * 8 + (idx & 7)])
                               : make_float4(0.f, 0.f, 0.f, 0.f);
        }
        __syncthreads();

        int jg = threadIdx.x & 31;
        int ng = threadIdx.x >> 5;
        const float* xb = sX + ng * 8 * 32;
        const float4* sW4 = reinterpret_cast<const float4*>(sW);

        float4 acc[8];
        #pragma unroll
        for (int i = 0; i < 8; i++) acc[i] = make_float4(0.f, 0.f, 0.f, 0.f);

        #pragma unroll 8
        for (int k = 0; k < 32; k++) {
            float4 wv = sW4[k * 32 + jg];
            #pragma unroll
            for (int i = 0; i < 8; i++) fma4(acc[i], xb[i * 32 + k], wv);
        }

        float4* dst4 = (jg < 16) ? reinterpret_cast<float4*>(g_p)
                                 : reinterpret_cast<float4*>(g_q);
        int jj = jg & 15;
        #pragma unroll
        for (int i = 0; i < 8; i++) {
            int n = n0 + ng * 8 + i;
            if (n < N) dst4[n * 16 + jj] = acc[i];
        }
        return;
    }

    // ---- u GEMM: 64 nodes x 64 outputs, K=64, acc[4] ----
    {
        int bid = id - gpq;
        float* sW = reinterpret_cast<float*>(smem_raw);            // 64*64 = 16KB
        float* sX = reinterpret_cast<float*>(smem_raw + 16384);    // 64*64 = 16KB

        for (int idx = threadIdx.x; idx < 64 * 64; idx += 256)
            sW[idx] = g_WuT[idx];

        int n0 = bid * 64;
        const float4* h4 = reinterpret_cast<const float4*>(h);
        float4* sX4 = reinterpret_cast<float4*>(sX);
        for (int idx = threadIdx.x; idx < 1024; idx += 256) {
            int n = n0 + (idx >> 4);
            sX4[idx] = (n < N) ? __ldg(&h4[n * 16 + (idx & 15)])
                               : make_float4(0.f, 0.f, 0.f, 0.f);
        }
        __syncthreads();

        int jg = threadIdx.x & 15;
        int ng = threadIdx.x >> 4;
        const float* xb = sX + ng * 4 * 64;
        const float4* sW4 = reinterpret_cast<const float4*>(sW);

        float4 acc[4];
        #pragma unroll
        for (int i = 0; i < 4; i++) acc[i] = make_float4(0.f, 0.f, 0.f, 0.f);

        #pragma unroll 8
        for (int k = 0; k < 64; k++) {
            float4 wv = sW4[k * 16 + jg];
            #pragma unroll
            for (int i = 0; i < 4; i++) fma4(acc[i], xb[i * 64 + k], wv);
        }

        float4* du4 = reinterpret_cast<float4*>(g_u);
        #pragma unroll
        for (int i = 0; i < 4; i++) {
            int n = n0 + ng * 4 + i;
            if (n < N) du4[n * 16 + jg] = acc[i];
        }
    }
}

// ---------------------------------------------------------------------------
// Launch 5: fused gather + finalize, FLATTENED 4-node edge walk.
// The 4 nodes of a warp-group have contiguous CSR ranges, so one loop walks
// [off[nb], off[nb+4]) with 4 accumulators selected by boundary compare —
// no per-node merge/compute between gathers, so loads stay in flight across
// node boundaries. Grid-striped one-wave grid kills wave quantization.
// ---------------------------------------------------------------------------
__global__ __launch_bounds__(256, 4) void gather_finalize_kernel(
    const float* __restrict__ h, float* __restrict__ out, int N, int nG)
{
    __shared__ float sW1cT[16 * 64];
    __shared__ float sW2T[64 * 64];
    __shared__ __align__(16) float sY[8][4 * 64];
    __shared__ float sEf[8][4 * 16];

    for (int idx = threadIdx.x; idx < 16 * 64; idx += 256) sW1cT[idx] = g_W1cT[idx];
    for (int idx = threadIdx.x; idx < 64 * 64; idx += 256) sW2T[idx]  = g_W2T[idx];
    __syncthreads();

    int lane = threadIdx.x & 31;
    int warp = threadIdx.x >> 5;
    int slot = lane >> 4;          // 0 or 1
    int f4   = lane & 15;          // float4 index within 64-float row
    const float4* u4 = reinterpret_cast<const float4*>(g_u);

    for (int g = blockIdx.x * 8 + warp; g < nG; g += gridDim.x * 8) {
        int nb = g * 4;
        int nA = nb, nB = min(nb + 1, N), nC = min(nb + 2, N), nD = min(nb + 3, N);
        int nE2 = min(nb + 4, N);
        int o0 = __ldg(&g_off[nA]);
        int o1 = __ldg(&g_off[nB]);
        int o2 = __ldg(&g_off[nC]);
        int o3 = __ldg(&g_off[nD]);
        int o4 = __ldg(&g_off[nE2]);

        float4 a0 = make_float4(0.f, 0.f, 0.f, 0.f);
        float4 a1 = a0, a2 = a0, a3 = a0;

        // ---- flattened edge walk: 8 edges per iter, 2 slots x unroll 4 ----
        int i = o0;
        for (; i + 8 <= o4; i += 8) {
            int p0 = i     + slot;
            int p1 = i + 2 + slot;
            int p2 = i + 4 + slot;
            int p3 = i + 6 + slot;
            int s0 = __ldg(&g_esrc[p0]);
            int s1 = __ldg(&g_esrc[p1]);
            int s2 = __ldg(&g_esrc[p2]);
            int s3 = __ldg(&g_esrc[p3]);
            float4 v0 = __ldg(&u4[s0 * 16 + f4]);
            float4 v1 = __ldg(&u4[s1 * 16 + f4]);
            float4 v2 = __ldg(&u4[s2 * 16 + f4]);
            float4 v3 = __ldg(&u4[s3 * 16 + f4]);
            accum_sel(p0, v0, o1, o2, o3, a0, a1, a2, a3);
            accum_sel(p1, v1, o1, o2, o3, a0, a1, a2, a3);
            accum_sel(p2, v2, o1, o2, o3, a0, a1, a2, a3);
            accum_sel(p3, v3, o1, o2, o3, a0, a1, a2, a3);
        }
        for (; i + 2 <= o4; i += 2) {
            int p = i + slot;
            int s = __ldg(&g_esrc[p]);
            float4 v = __ldg(&u4[s * 16 + f4]);
            accum_sel(p, v, o1, o2, o3, a0, a1, a2, a3);
        }
        if (i < o4 && slot == 0) {
            int s = __ldg(&g_esrc[i]);
            float4 v = __ldg(&u4[s * 16 + f4]);
            accum_sel(i, v, o1, o2, o3, a0, a1, a2, a3);
        }

        // ---- merge slots, stage sums + ef sums ----
        #define MERGE4(a) \
            (a).x += __shfl_xor_sync(0xffffffffu, (a).x, 16); \
            (a).y += __shfl_xor_sync(0xffffffffu, (a).y, 16); \
            (a).z += __shfl_xor_sync(0xffffffffu, (a).z, 16); \
            (a).w += __shfl_xor_sync(0xffffffffu, (a).w, 16);
        MERGE4(a0) MERGE4(a1) MERGE4(a2) MERGE4(a3)
        #undef MERGE4

        if (lane < 16) {
            reinterpret_cast<float4*>(&sY[warp][0])[f4]       = a0;
            reinterpret_cast<float4*>(&sY[warp][64])[f4]      = a1;
            reinterpret_cast<float4*>(&sY[warp][128])[f4]     = a2;
            reinterpret_cast<float4*>(&sY[warp][192])[f4]     = a3;
            #pragma unroll
            for (int m = 0; m < 4; m++) {
                int n = nb + m;
                sEf[warp][m * 16 + lane] =
                    (n < N) ? __ldg(&g_efs[n * 16 + lane]) : 0.f;
            }
        }
        __syncwarp();

        // ---- phase 2: y = msum + p + deg*q + W1c@efs (4-node batched) ----
        float dgf[4] = { (float)(o1 - o0), (float)(o2 - o1),
                         (float)(o3 - o2), (float)(o4 - o3) };
        float y0[4], y1[4];
        #pragma unroll
        for (int m = 0; m < 4; m++) {
            int n = min(nb + m, N - 1);
            y0[m] = sY[warp][m * 64 + lane]
                  + g_p[n * 64 + lane]      + dgf[m] * g_q[n * 64 + lane];
            y1[m] = sY[warp][m * 64 + lane + 32]
                  + g_p[n * 64 + lane + 32] + dgf[m] * g_q[n * 64 + lane + 32];
        }
        #pragma unroll
        for (int k = 0; k < 16; k++) {
            float w0 = sW1cT[k * 64 + lane];
            float w1 = sW1cT[k * 64 + lane + 32];
            #pragma unroll
            for (int m = 0; m < 4; m++) {
                float e = sEf[warp][m * 16 + k];
                y0[m] = fmaf(e, w0, y0[m]);
                y1[m] = fmaf(e, w1, y1[m]);
            }
        }
        #pragma unroll
        for (int m = 0; m < 4; m++) {
            sY[warp][m * 64 + lane]      = fmaxf(y0[m], 0.f);
            sY[warp][m * 64 + lane + 32] = fmaxf(y1[m], 0.f);
        }
        __syncwarp();

        // ---- phase 3: out = relu(y) @ W2^T ----
        float q0[4] = {0.f, 0.f, 0.f, 0.f};
        float q1[4] = {0.f, 0.f, 0.f, 0.f};
        #pragma unroll
        for (int j = 0; j < 64; j++) {
            float w0 = sW2T[j * 64 + lane];
            float w1 = sW2T[j * 64 + lane + 32];
            #pragma unroll
            for (int m = 0; m < 4; m++) {
                float yj = sY[warp][m * 64 + j];
                q0[m] = fmaf(yj, w0, q0[m]);
                q1[m] = fmaf(yj, w1, q1[m]);
            }
        }

        #pragma unroll
        for (int m = 0; m < 4; m++) {
            int n = nb + m;
            if (n < N) {
                if (dgf[m] > 0.f) {
                    out[n * 64 + lane]      = q0[m];
                    out[n * 64 + lane + 32] = q1[m];
                } else {
                    out[n * 64 + lane]      = h[n * 64 + lane];
                    out[n * 64 + lane + 32] = h[n * 64 + lane + 32];
                }
            }
        }
        __syncwarp();   // protect sY/sEf before next group's staging
    }
}

// ---------------------------------------------------------------------------
extern "C" void kernel_launch(void* const* d_in, const int* in_sizes, int n_in,
                              void* d_out, int out_size)
{
    const float* h  = (const float*)d_in[0];
    const float* nf = (const float*)d_in[1];
    const float* ef = (const float*)d_in[2];
    const int*  src = (const int*)d_in[3];
    const int*  dst = (const int*)d_in[4];
    const float* W1 = (const float*)d_in[5];
    const float* W2 = (const float*)d_in[6];
    float* out = (float*)d_out;

    int N = in_sizes[1] / 32;   // nf is [N, 32]
    int E = in_sizes[3];        // src is [E]

    int ge   = (E + 255) / 256;        // hist / scatter blocks
    int gsc  = (NN + 1023) / 1024;     // 49
    int gpq  = (N + 63) / 64;
    int gu   = (N + 63) / 64;
    int G    = ge + gpq + gu;
    int nG   = (N + 3) / 4;            // node groups for gather
    int gf   = 592;                    // one-wave grid (148 SMs x 4 blocks)

    hist_kernel<<<ge, 256>>>(dst, W1, W2, E);
    scan1_kernel<<<gsc, 1024>>>();
    scan2_kernel<<<gsc, 1024>>>(E);
    fused4_kernel<<<G, 256>>>(src, dst, ef, nf, h, N, E, ge, gpq, G);
    gather_finalize_kernel<<<gf, 256>>>(h, out, N, nG);
}